// round 8
// baseline (speedup 1.0000x reference)
#include <cuda_runtime.h>
#include <math.h>

// Problem constants
#define Bz 8
#define Tz 512
#define Ez 64
#define Hz 128
#define TC 32     // tokens per CTA
#define NC 16     // chunks per batch
#define NCTA (Bz*NC)

// Pitches (floats). P1/PK = 68 (17 odd -> conflict-free LDS.128 rows),
// P2/PH = 132 (33 odd -> conflict-free rows; col scalar 4-way max).
#define P1 68
#define PK 68
#define P2 132
#define PH 132

// Per-CTA partial layout (floats): D-weighted grads only
#define OF2_W1D 0
#define OF2_B1D 8192
#define OF2_W2D 8320
#define OF2_B2D 16512
#define PARTSZ2 16576

// Output offsets
#define O_LOSS 0
#define O_MW1  512
#define O_MB1  66048
#define O_MW2  67072
#define O_MB2  132608
#define O_SW1  133120
#define O_SB1  198656
#define O_SW2  199680
#define O_SB2  265216

#define LNETA  (-0.0512932943875506f)   // ln(0.95)
#define LNBE   (-6.8564619845945864f)   // ln(0.001) - ln(0.95)
#define INV949 (1.0537407798735f)       // 1/(0.95-0.001)

// Scratch (device globals)
__device__ __align__(16) float g_np[2*NCTA*Ez];
__device__ __align__(16) float g_lossp[Bz*Tz];
__device__ __align__(16) float g_part[NCTA*PARTSZ2];
__device__ __align__(16) float g_corr[Bz*PARTSZ2];
__device__ unsigned g_count;
__device__ volatile unsigned g_phase;

__device__ __forceinline__ void grid_barrier(int tid) {
    __threadfence();
    __syncthreads();
    if (tid == 0) {
        unsigned my = g_phase;
        unsigned old = atomicAdd(&g_count, 1);
        if (old == NCTA - 1) {
            g_count = 0;
            __threadfence();
            atomicAdd((unsigned*)&g_phase, 1);
        } else {
            while (g_phase == my) { }
        }
        __threadfence();
    }
    __syncthreads();
}

// ---------------------------------------------------------------------------
// Single fused kernel. 128 CTAs x 512 threads, ~142KB smem -> 1 CTA/SM.
// proj/z phases use lane=token layout: weight LDS are broadcasts.
// ---------------------------------------------------------------------------
#define SM_FLOATS 36448
__global__ __launch_bounds__(512, 1) void k_main(const float* __restrict__ x,
                                                 const float* __restrict__ WK,
                                                 const float* __restrict__ WV,
                                                 const float* __restrict__ W1,
                                                 const float* __restrict__ b1,
                                                 const float* __restrict__ W2,
                                                 const float* __restrict__ b2,
                                                 const float* __restrict__ SW1,
                                                 const float* __restrict__ Sb1,
                                                 const float* __restrict__ SW2,
                                                 const float* __restrict__ Sb2,
                                                 float* __restrict__ out) {
    extern __shared__ float sm[];
    // Region A (8704): phase0 = WK|WV ; later = W1
    float* sWK  = sm;                 // 64 x P1 = 4352
    float* sWV  = sm + 4352;
    float* sW1  = sm;                 // 128 x P1 overlay
    // Region B (8448): phase0 = x ; later = W2
    float* sx   = sm + 8704;          // 32 x PK = 2176 (phase0 only)
    float* sW2  = sm + 8704;          // 64 x P2 = 8448 overlay
    float* sk   = sm + 17152;         // 32 x PK = 2176
    float* sv   = sk  + 2176;         // 32 x PK = 2176
    float* sh   = sv  + 2176;         // 32 x PH = 4224
    float* ss   = sh  + 4224;         // 32 x PH
    float* sdy  = ss  + 4224;         // 32 x 64 = 2048
    float* sdz  = sdy + 2048;         // 32 x PH = 4224
    float* scD  = sdz + 4224;         // 32
    float* scR  = scD + 32;           // 32 (corr ratio cc/cd)
    float* sinvk= scR + 32;           // 64
    float* sinvv= sinvk + 64;         // 64
    float* sloss= sinvv + 64;         // 32  -> total 36448

    const int bid = blockIdx.x;
    const int b   = bid >> 4;
    const int t0  = (bid & 15) * TC;
    const int tid = threadIdx.x;
    const int lane = tid & 31, wp = tid >> 5;   // 16 warps

    // ---- phase 0 loads ----
    #pragma unroll
    for (int i = tid*4; i < 4096; i += 2048) {
        int e = i >> 6, j = i & 63;
        *(float4*)&sWK[e*P1 + j] = *(const float4*)&WK[i];
        *(float4*)&sWV[e*P1 + j] = *(const float4*)&WV[i];
    }
    {
        int i = tid*4;
        int t = i >> 6, e4 = i & 63;
        *(float4*)&sx[t*PK + e4] = *(const float4*)&x[(b*Tz + t0)*64 + i];
    }
    if (tid >= 128 && tid < 160) {
        int tl = tid - 128;
        float n1 = (float)(Tz - (t0 + tl));
        scD[tl] = -0.05f * __expf(n1 * LNETA);
        scR[tl] = -INV949 * __expf(n1 * LNBE);   // cc/cd
    }
    __syncthreads();

    // ---- phase 0: silu projections. lane = token, warp owns 8 rows ----
    {
        const int rb = (wp & 7) * 8;
        const bool isK = (wp < 8);
        const float* sW = isK ? sWK : sWV;
        float acc[8];
        #pragma unroll
        for (int r = 0; r < 8; r++) acc[r] = 0.f;
        for (int j = 0; j < 64; j += 4) {
            float4 xq = *(const float4*)&sx[lane*PK + j];
            #pragma unroll
            for (int r = 0; r < 8; r++) {
                float4 w = *(const float4*)&sW[(rb + r)*P1 + j];
                acc[r] += w.x*xq.x + w.y*xq.y + w.z*xq.z + w.w*xq.w;
            }
        }
        float val[8];
        #pragma unroll
        for (int r = 0; r < 8; r++) {
            float z = acc[r];
            val[r] = z / (1.f + __expf(-z));
        }
        float* dst = isK ? sk : sv;
        *(float4*)&dst[lane*PK + rb] =
            make_float4(val[0], val[1], val[2], val[3]);
        *(float4*)&dst[lane*PK + rb + 4] =
            make_float4(val[4], val[5], val[6], val[7]);
        float* nrm = isK ? sinvk : sinvv;
        #pragma unroll
        for (int r = 0; r < 8; r++) {
            float q = val[r] * val[r];
            #pragma unroll
            for (int o = 16; o; o >>= 1) q += __shfl_xor_sync(0xffffffffu, q, o);
            if (lane == 0) nrm[rb + r] = q;   // unique (warp,r) -> e
        }
    }
    __syncthreads();

    // publish norm partials
    if (tid < 64)       g_np[bid*64 + tid] = sinvk[tid];
    else if (tid < 128) g_np[(NCTA + bid)*64 + tid - 64] = sinvv[tid - 64];

    // ---- grid barrier #1 (W1/W2 loads overlap the spin) ----
    __threadfence();
    __syncthreads();
    if (tid == 0) {
        unsigned my = g_phase;
        unsigned old = atomicAdd(&g_count, 1);
        if (old == NCTA - 1) {
            g_count = 0;
            __threadfence();
            atomicAdd((unsigned*)&g_phase, 1);
        } else {
            while (g_phase == my) { }
        }
        __threadfence();
    }
    #pragma unroll
    for (int i = tid*4; i < 8192; i += 2048)
        *(float4*)&sW1[(i >> 6)*P1 + (i & 63)] = *(const float4*)&W1[b*8192 + i];
    #pragma unroll
    for (int i = tid*4; i < 8192; i += 2048)
        *(float4*)&sW2[(i >> 7)*P2 + (i & 127)] = *(const float4*)&W2[b*8192 + i];
    __syncthreads();

    // ---- reduce norms ----
    if (tid < 64) {
        float s = 0.f, s2 = 0.f;
        #pragma unroll
        for (int c = 0; c < NC; c++) {
            s  += g_np[(b*NC + c)*64 + tid];
            s2 += g_np[(NCTA + b*NC + c)*64 + tid];
        }
        sinvk[tid] = (s  > 0.f) ? rsqrtf(s)  : 0.f;
        sinvv[tid] = (s2 > 0.f) ? rsqrtf(s2) : 0.f;
    }
    __syncthreads();

    // ---- normalize k, v (pitch PK) ----
    {
        int t = tid >> 4, e4 = (tid & 15) * 4;
        float4 q = *(const float4*)&sk[t*PK + e4];
        q.x *= sinvk[e4]; q.y *= sinvk[e4+1]; q.z *= sinvk[e4+2]; q.w *= sinvk[e4+3];
        *(float4*)&sk[t*PK + e4] = q;
        float4 p = *(const float4*)&sv[t*PK + e4];
        p.x *= sinvv[e4]; p.y *= sinvv[e4+1]; p.z *= sinvv[e4+2]; p.w *= sinvv[e4+3];
        *(float4*)&sv[t*PK + e4] = p;
    }
    __syncthreads();

    // ---- z = W1 k + b1 ; h = silu(z). lane = token, warp owns 8 h-rows ----
    {
        const int hb = wp * 8;
        float acc[8];
        #pragma unroll
        for (int r = 0; r < 8; r++) acc[r] = b1[b*128 + hb + r];
        for (int j = 0; j < 64; j += 4) {
            float4 kq = *(const float4*)&sk[lane*PK + j];
            #pragma unroll
            for (int r = 0; r < 8; r++) {
                float4 w = *(const float4*)&sW1[(hb + r)*P1 + j];
                acc[r] += w.x*kq.x + w.y*kq.y + w.z*kq.z + w.w*kq.w;
            }
        }
        float hv[8], sgv[8];
        #pragma unroll
        for (int r = 0; r < 8; r++) {
            float z = acc[r];
            float sg = 1.f / (1.f + __expf(-z));
            sgv[r] = sg;
            hv[r]  = z * sg;
        }
        *(float4*)&sh[lane*PH + hb]     = make_float4(hv[0], hv[1], hv[2], hv[3]);
        *(float4*)&sh[lane*PH + hb + 4] = make_float4(hv[4], hv[5], hv[6], hv[7]);
        *(float4*)&ss[lane*PH + hb]     = make_float4(sgv[0], sgv[1], sgv[2], sgv[3]);
        *(float4*)&ss[lane*PH + hb + 4] = make_float4(sgv[4], sgv[5], sgv[6], sgv[7]);
    }
    __syncthreads();   // cross-warp: y-phase consumes full token rows

    // ---- y = W2 h + b2 ; dy = (y-v)/256 * cD[t] (prefold) ; loss ----
    {
        float acc[2][2];
        #pragma unroll
        for (int r = 0; r < 2; r++) {
            float bv = b2[b*64 + lane + 32*r];
            acc[r][0] = bv; acc[r][1] = bv;
        }
        for (int j = 0; j < 128; j += 4) {
            float hv[2][4];
            #pragma unroll
            for (int tt = 0; tt < 2; tt++) {
                float4 q = *(const float4*)&sh[(wp*2 + tt)*PH + j];
                hv[tt][0] = q.x; hv[tt][1] = q.y; hv[tt][2] = q.z; hv[tt][3] = q.w;
            }
            float4 w40 = *(const float4*)&sW2[(lane     )*P2 + j];
            float4 w41 = *(const float4*)&sW2[(lane + 32)*P2 + j];
            const float* w0 = (const float*)&w40;
            const float* w1 = (const float*)&w41;
            #pragma unroll
            for (int jj = 0; jj < 4; jj++) {
                acc[0][0] += w0[jj] * hv[0][jj];
                acc[0][1] += w0[jj] * hv[1][jj];
                acc[1][0] += w1[jj] * hv[0][jj];
                acc[1][1] += w1[jj] * hv[1][jj];
            }
        }
        #pragma unroll
        for (int tt = 0; tt < 2; tt++) {
            int t = wp*2 + tt;
            float fold = (1.f/256.f) * scD[t];
            float l = 0.f;
            #pragma unroll
            for (int r = 0; r < 2; r++) {
                int e = lane + 32*r;
                float d = acc[r][tt] - sv[t*PK + e];
                sdy[t*64 + e] = d * fold;
                l += d * d;
            }
            #pragma unroll
            for (int o = 16; o; o >>= 1) l += __shfl_xor_sync(0xffffffffu, l, o);
            if (lane == 0) sloss[t] = l;
        }
    }
    __syncwarp();   // sdy rows warp-private

    // ---- dh = W2^T dy ; dz = dh * dsilu (cD already folded via dy) ----
    {
        float acc[4][2];
        #pragma unroll
        for (int r = 0; r < 4; r++) { acc[r][0] = 0.f; acc[r][1] = 0.f; }
        for (int e = 0; e < 64; e += 4) {
            float dv[2][4];
            #pragma unroll
            for (int tt = 0; tt < 2; tt++) {
                float4 q = *(const float4*)&sdy[(wp*2 + tt)*64 + e];
                dv[tt][0] = q.x; dv[tt][1] = q.y; dv[tt][2] = q.z; dv[tt][3] = q.w;
            }
            #pragma unroll
            for (int ee = 0; ee < 4; ee++) {
                float wv[4];
                #pragma unroll
                for (int r = 0; r < 4; r++) wv[r] = sW2[(e + ee)*P2 + lane + 32*r];
                #pragma unroll
                for (int r = 0; r < 4; r++) {
                    acc[r][0] += wv[r] * dv[0][ee];
                    acc[r][1] += wv[r] * dv[1][ee];
                }
            }
        }
        #pragma unroll
        for (int r = 0; r < 4; r++)
            #pragma unroll
            for (int tt = 0; tt < 2; tt++) {
                int idx = (wp*2 + tt)*PH + lane + 32*r;
                float sg = ss[idx], hv = sh[idx];
                sdz[idx] = acc[r][tt] * (sg + hv * (1.f - sg));
            }
    }
    __syncthreads();

    // ---- D-weighted outer products (weights prefolded into dz/dy) ----
    const int e0 = (tid & 15) * 4;
    const int h0 = (tid >> 4) * 4;
    float a1[4][4], a2[4][4];
    #pragma unroll
    for (int i = 0; i < 4; i++)
        #pragma unroll
        for (int j = 0; j < 4; j++) { a1[i][j] = 0.f; a2[j][i] = 0.f; }

    for (int t = 0; t < TC; t++) {
        float4 kq = *(const float4*)&sk[t*PK + e0];
        float ks[4] = {kq.x, kq.y, kq.z, kq.w};
        float4 zq = *(const float4*)&sdz[t*PH + h0];
        float dzv[4] = {zq.x, zq.y, zq.z, zq.w};
        #pragma unroll
        for (int i = 0; i < 4; i++)
            #pragma unroll
            for (int j = 0; j < 4; j++) a1[i][j] += dzv[i] * ks[j];
        float4 dq = *(const float4*)&sdy[t*64 + e0];
        float dys[4] = {dq.x, dq.y, dq.z, dq.w};
        float4 hq = *(const float4*)&sh[t*PH + h0];
        float hv[4] = {hq.x, hq.y, hq.z, hq.w};
        #pragma unroll
        for (int j = 0; j < 4; j++)
            #pragma unroll
            for (int i = 0; i < 4; i++) a2[j][i] += dys[j] * hv[i];
    }

    float* p = g_part + (size_t)bid * PARTSZ2;
    #pragma unroll
    for (int i = 0; i < 4; i++)
        *(float4*)&p[OF2_W1D + (h0 + i)*64 + e0] =
            make_float4(a1[i][0], a1[i][1], a1[i][2], a1[i][3]);
    #pragma unroll
    for (int j = 0; j < 4; j++)
        *(float4*)&p[OF2_W2D + (e0 + j)*128 + h0] =
            make_float4(a2[j][0], a2[j][1], a2[j][2], a2[j][3]);
    if (tid < 128) {
        float aD = 0.f;
        for (int t = 0; t < TC; t++) aD += sdz[t*PH + tid];
        p[OF2_B1D + tid] = aD;
    } else if (tid < 192) {
        int e = tid - 128;
        float aD = 0.f;
        for (int t = 0; t < TC; t++) aD += sdy[t*64 + e];
        p[OF2_B2D + e] = aD;
    }
    if (tid < TC) g_lossp[b*Tz + t0 + tid] = sloss[tid];

    // ---- correction (last chunk per batch; ratio scR = cc/cd) ----
    if ((bid & 15) == 15) {
        #pragma unroll
        for (int i = 0; i < 4; i++)
            #pragma unroll
            for (int j = 0; j < 4; j++) { a1[i][j] = 0.f; a2[j][i] = 0.f; }
        for (int t = 16; t < TC; t++) {
            float rr = scR[t];
            float4 kq = *(const float4*)&sk[t*PK + e0];
            float ks[4] = {rr*kq.x, rr*kq.y, rr*kq.z, rr*kq.w};
            float4 zq = *(const float4*)&sdz[t*PH + h0];
            float dzv[4] = {zq.x, zq.y, zq.z, zq.w};
            #pragma unroll
            for (int i = 0; i < 4; i++)
                #pragma unroll
                for (int j = 0; j < 4; j++) a1[i][j] += dzv[i] * ks[j];
            float4 dq = *(const float4*)&sdy[t*64 + e0];
            float dys[4] = {rr*dq.x, rr*dq.y, rr*dq.z, rr*dq.w};
            float4 hq = *(const float4*)&sh[t*PH + h0];
            float hv[4] = {hq.x, hq.y, hq.z, hq.w};
            #pragma unroll
            for (int j = 0; j < 4; j++)
                #pragma unroll
                for (int i = 0; i < 4; i++) a2[j][i] += dys[j] * hv[i];
        }
        float* q = g_corr + (size_t)b * PARTSZ2;
        #pragma unroll
        for (int i = 0; i < 4; i++)
            *(float4*)&q[OF2_W1D + (h0 + i)*64 + e0] =
                make_float4(a1[i][0], a1[i][1], a1[i][2], a1[i][3]);
        #pragma unroll
        for (int j = 0; j < 4; j++)
            *(float4*)&q[OF2_W2D + (e0 + j)*128 + h0] =
                make_float4(a2[j][0], a2[j][1], a2[j][2], a2[j][3]);
        if (tid < 128) {
            float aC = 0.f;
            for (int t = 16; t < TC; t++) aC += scR[t] * sdz[t*PH + tid];
            q[OF2_B1D + tid] = aC;
        } else if (tid < 192) {
            int e = tid - 128;
            float aC = 0.f;
            for (int t = 16; t < TC; t++) aC += scR[t] * sdy[t*64 + e];
            q[OF2_B2D + e] = aC;
        }
    }

    // ---- grid barrier #2, then fused output reduction ----
    grid_barrier(tid);

    const float qT = __expf(-26.262166726f);    // 0.95^512
    const float aT = qT * 1.0010537407f;        // qT/(1-beta/eta)
    int gt = bid * 512 + tid;
    if (gt < 512) {
        float s = 0.f;
        #pragma unroll
        for (int bb = 0; bb < Bz; bb++) s += g_lossp[bb*Tz + gt];
        out[O_LOSS + gt] = s * (1.f/512.f);
        return;
    }
    int j = gt - 512;
    int ofD, nvec_b, segM, segS;
    const float* S0p;
    if (j < 16384) {
        ofD = OF2_W1D; nvec_b = 2048; segM = O_MW1; segS = O_SW1; S0p = SW1;
    } else if ((j -= 16384) < 256) {
        ofD = OF2_B1D; nvec_b = 32;   segM = O_MB1; segS = O_SB1; S0p = Sb1;
    } else if ((j -= 256) < 16384) {
        ofD = OF2_W2D; nvec_b = 2048; segM = O_MW2; segS = O_SW2; S0p = SW2;
    } else if ((j -= 16384) < 128) {
        ofD = OF2_B2D; nvec_b = 16;   segM = O_MB2; segS = O_SB2; S0p = Sb2;
    } else return;

    int bb = j / nvec_b;
    int r = (j - bb*nvec_b) * 4;
    const float* pp = g_part + (size_t)(bb*NC) * PARTSZ2 + ofD + r;
    float4 rD = make_float4(0.f, 0.f, 0.f, 0.f);
    #pragma unroll
    for (int c = 0; c < NC; c++) {
        float4 v = *(const float4*)(pp + (size_t)c * PARTSZ2);
        rD.x += v.x; rD.y += v.y; rD.z += v.z; rD.w += v.w;
    }
    float4 cr = *(const float4*)(g_corr + (size_t)bb * PARTSZ2 + ofD + r);
    int gidx = bb * (nvec_b*4) + r;
    float4 s0 = *(const float4*)(S0p + gidx);
    float4 M, S;
    M.x = aT*s0.x + rD.x*INV949 + cr.x;  S.x = qT*s0.x + rD.x;
    M.y = aT*s0.y + rD.y*INV949 + cr.y;  S.y = qT*s0.y + rD.y;
    M.z = aT*s0.z + rD.z*INV949 + cr.z;  S.z = qT*s0.z + rD.z;
    M.w = aT*s0.w + rD.w*INV949 + cr.w;  S.w = qT*s0.w + rD.w;
    *(float4*)(out + segM + gidx) = M;
    *(float4*)(out + segS + gidx) = S;
}

extern "C" void kernel_launch(void* const* d_in, const int* in_sizes, int n_in,
                              void* d_out, int out_size) {
    const float* x   = (const float*)d_in[0];
    const float* WK  = (const float*)d_in[1];
    const float* WV  = (const float*)d_in[2];
    const float* W1  = (const float*)d_in[3];
    const float* b1  = (const float*)d_in[4];
    const float* W2  = (const float*)d_in[5];
    const float* b2  = (const float*)d_in[6];
    const float* SW1 = (const float*)d_in[7];
    const float* Sb1 = (const float*)d_in[8];
    const float* SW2 = (const float*)d_in[9];
    const float* Sb2 = (const float*)d_in[10];
    float* out = (float*)d_out;

    static const size_t smem_main = SM_FLOATS * sizeof(float);
    cudaFuncSetAttribute(k_main, cudaFuncAttributeMaxDynamicSharedMemorySize,
                         (int)smem_main);

    k_main<<<NCTA, 512, smem_main>>>(x, WK, WV, W1, b1, W2, b2,
                                     SW1, Sb1, SW2, Sb2, out);
}